// round 3
// baseline (speedup 1.0000x reference)
#include <cuda_runtime.h>
#include <math.h>

#define NB 16
#define NT 64
#define NV 32000
#define NE 256
#define NH 1024
#define NG 4096   // 4*H

// ---------------- device scratch (no allocs allowed) ----------------
__device__ float g_zx_enc[NB*NT*NG];     // precomputed x@W + bias (encoder)
__device__ float g_zx_dec[NB*NT*NG];     // precomputed x@W + bias (decoder)
__device__ float g_memory[NB*NT*NH];
__device__ float g_keys[NB*NT*NH];
__device__ float g_dec_out[NB*NT*NH];
__device__ float g_zpart[16*NB*NG];      // skinny-gemm K-split partials (4H wide)
__device__ float g_qpart[16*NB*NH];
__device__ float g_apart[16*NB*NH];
__device__ float g_h[NB*NH];
__device__ float g_c[NB*NH];
__device__ float g_attn_h[NB*2*NH];      // [attn(1024) | h(1024)] per batch (decoder input)
__device__ float g_h_ctx[NB*2*NH];       // [h2(1024) | context(1024)] per batch
__device__ float g_scores[NB*NT];

__device__ __forceinline__ float sigm(float x){ return 1.f/(1.f+expf(-x)); }

// =====================================================================
// Big tiled SGEMM: C[M,N] = gatherA[M,K] @ W[K,N] (+bias). 128x128 tile,
// 256 threads, 8x8 per thread, BK=8. M,N,K assumed multiples of tile dims.
// =====================================================================
__global__ __launch_bounds__(256) void sgemm_nn(
    int M, int N, int K,
    const float* __restrict__ A, const float* __restrict__ W,
    const float* __restrict__ bias, float* __restrict__ C,
    const int* __restrict__ gather)
{
  __shared__ float As[8][128];
  __shared__ float Bs[8][128];
  const int tid = threadIdx.x;
  const int tx = tid & 15;
  const int ty = tid >> 4;
  const int mbase = blockIdx.y * 128;
  const int nbase = blockIdx.x * 128;
  const int arow = tid >> 1;
  const int acol = (tid & 1) << 2;
  const int brow = tid >> 5;
  const int bcol = (tid & 31) << 2;
  const int arI = mbase + arow;
  const float* Ap = A + (size_t)(gather ? gather[arI] : arI) * K + acol;
  const float* Wp = W + (size_t)brow * N + nbase + bcol;

  float acc[8][8];
#pragma unroll
  for (int i = 0; i < 8; i++)
#pragma unroll
    for (int j = 0; j < 8; j++) acc[i][j] = 0.f;

  for (int k0 = 0; k0 < K; k0 += 8) {
    float4 av = *(const float4*)(Ap + k0);
    As[acol+0][arow] = av.x; As[acol+1][arow] = av.y;
    As[acol+2][arow] = av.z; As[acol+3][arow] = av.w;
    float4 bv = *(const float4*)(Wp + (size_t)k0 * N);
    *(float4*)&Bs[brow][bcol] = bv;
    __syncthreads();
#pragma unroll
    for (int kk = 0; kk < 8; kk++) {
      float ar[8], br[8];
#pragma unroll
      for (int i = 0; i < 8; i++) ar[i] = As[kk][ty*8 + i];
#pragma unroll
      for (int j = 0; j < 8; j++) br[j] = Bs[kk][tx*8 + j];
#pragma unroll
      for (int i = 0; i < 8; i++)
#pragma unroll
        for (int j = 0; j < 8; j++) acc[i][j] += ar[i] * br[j];
    }
    __syncthreads();
  }

  float bvals[8];
#pragma unroll
  for (int j = 0; j < 8; j++) bvals[j] = bias ? bias[nbase + tx*8 + j] : 0.f;
#pragma unroll
  for (int i = 0; i < 8; i++) {
    size_t ro = (size_t)(mbase + ty*8 + i) * N + nbase + tx*8;
#pragma unroll
    for (int j = 0; j < 8; j += 4) {
      float4 v;
      v.x = acc[i][j+0] + bvals[j+0];
      v.y = acc[i][j+1] + bvals[j+1];
      v.z = acc[i][j+2] + bvals[j+2];
      v.w = acc[i][j+3] + bvals[j+3];
      *(float4*)(C + ro + j) = v;
    }
  }
}

// =====================================================================
// Skinny GEMM for M=16 recurrent matmuls, K-split, deterministic partials.
// part[(blockIdx.y*16+b)*N + n] = sum_{k in this block's K chunk} y[b][k]*W[k][n]
// grid = (N/128, KSPLIT); block = 256 (8 warps x 32 lanes, 4 cols/lane).
// Kblk = K/gridDim.y must be <= 128 and divisible by 8.
// =====================================================================
__global__ __launch_bounds__(256) void skinny_gemm(
    const float* __restrict__ y, int ystride,
    const float* __restrict__ W, int ldw,
    float* __restrict__ part, int N, int K)
{
  __shared__ __align__(16) float smem[8192];
  const int tid  = threadIdx.x;
  const int wid  = tid >> 5;
  const int lane = tid & 31;
  const int Kblk  = K / gridDim.y;
  const int kbase = blockIdx.y * Kblk;
  const int c0    = blockIdx.x * 128 + lane * 4;

  // load y slab transposed into smem: ys[kl*16 + b]
  for (int idx = tid; idx < Kblk * 16; idx += 256) {
    int b = idx / Kblk;
    int kl = idx - b * Kblk;
    smem[kl*16 + b] = y[b * ystride + kbase + kl];
  }
  __syncthreads();

  const int kchunk = Kblk >> 3;
  const int ks0 = wid * kchunk;
  float4 acc[16];
#pragma unroll
  for (int b = 0; b < 16; b++) acc[b] = make_float4(0.f, 0.f, 0.f, 0.f);

  const float* Wp = W + (size_t)(kbase + ks0) * ldw + c0;
  const float4* yr = (const float4*)(smem + ks0 * 16);
  for (int k = 0; k < kchunk; k++) {
    float4 wv = *(const float4*)Wp;
    Wp += ldw;
#pragma unroll
    for (int bq = 0; bq < 4; bq++) {
      float4 yv = yr[bq];
      float ys4[4] = {yv.x, yv.y, yv.z, yv.w};
#pragma unroll
      for (int q = 0; q < 4; q++) {
        acc[4*bq+q].x += ys4[q] * wv.x;
        acc[4*bq+q].y += ys4[q] * wv.y;
        acc[4*bq+q].z += ys4[q] * wv.z;
        acc[4*bq+q].w += ys4[q] * wv.w;
      }
    }
    yr += 4;
  }

  // cross-warp tree reduction in smem (conflict-free layout: red[b][slot])
  float4* red = (float4*)smem;   // [16][128] float4
#pragma unroll
  for (int s = 4; s > 0; s >>= 1) {
    __syncthreads();
    if (wid >= s && wid < 2*s) {
      int slot = (wid - s) * 32 + lane;
#pragma unroll
      for (int b = 0; b < 16; b++) red[b*128 + slot] = acc[b];
    }
    __syncthreads();
    if (wid < s) {
      int slot = wid * 32 + lane;
#pragma unroll
      for (int b = 0; b < 16; b++) {
        float4 r = red[b*128 + slot];
        acc[b].x += r.x; acc[b].y += r.y; acc[b].z += r.z; acc[b].w += r.w;
      }
    }
  }

  if (wid == 0) {
#pragma unroll
    for (int b = 0; b < 16; b++)
      *(float4*)(part + (size_t)(blockIdx.y*16 + b) * N + c0) = acc[b];
  }
}

// =====================================================================
// Elementwise / small kernels
// =====================================================================
__global__ void zero_state()
{
  int idx = blockIdx.x * 256 + threadIdx.x;   // 16384
  g_h[idx] = 0.f;
  g_c[idx] = 0.f;
}

__global__ void enc_step_gates(int t, int nsplit, const int* __restrict__ enc_len)
{
  int idx = blockIdx.x * 256 + threadIdx.x;   // 16384
  int b = idx >> 10, j = idx & 1023;
  size_t zo = (size_t)(b*NT + t) * NG + j;
  float zi = g_zx_enc[zo], zj = g_zx_enc[zo+1024];
  float zf = g_zx_enc[zo+2048], zoo = g_zx_enc[zo+3072];
  for (int s = 0; s < nsplit; s++) {
    size_t po = (size_t)(s*16 + b) * NG + j;
    zi += g_zpart[po]; zj += g_zpart[po+1024];
    zf += g_zpart[po+2048]; zoo += g_zpart[po+3072];
  }
  float cn = g_c[idx] * sigm(zf + 1.f) + sigm(zi) * tanhf(zj);
  float hn = tanhf(cn) * sigm(zoo);
  bool valid = t < enc_len[b];
  if (valid) { g_h[idx] = hn; g_c[idx] = cn; }
  g_memory[(size_t)(b*NT + t) * NH + j] = valid ? hn : 0.f;
}

__global__ void dec_init()
{
  int idx = blockIdx.x * 256 + threadIdx.x;   // 32768
  int b = idx >> 11, j = idx & 2047;
  g_attn_h[idx] = (j < 1024) ? 0.f : g_h[b*NH + (j - 1024)];
}

__global__ void dec_step_gates(int t, int nsplit)
{
  int idx = blockIdx.x * 256 + threadIdx.x;   // 16384
  int b = idx >> 10, j = idx & 1023;
  size_t zo = (size_t)(b*NT + t) * NG + j;
  float zi = g_zx_dec[zo], zj = g_zx_dec[zo+1024];
  float zf = g_zx_dec[zo+2048], zoo = g_zx_dec[zo+3072];
  for (int s = 0; s < nsplit; s++) {
    size_t po = (size_t)(s*16 + b) * NG + j;
    zi += g_zpart[po]; zj += g_zpart[po+1024];
    zf += g_zpart[po+2048]; zoo += g_zpart[po+3072];
  }
  float cn = g_c[idx] * sigm(zf + 1.f) + sigm(zi) * tanhf(zj);
  float hn = tanhf(cn) * sigm(zoo);
  g_c[idx] = cn;
  g_attn_h[b*2*NH + NH + j] = hn;   // h slot for next step's recurrent input
  g_h_ctx[b*2*NH + j] = hn;         // h2 slot for query/attn gemms
}

__global__ __launch_bounds__(256) void attn_scores(
    int nsplit, const int* __restrict__ enc_len, const float* __restrict__ v_att)
{
  __shared__ float sq[NH];
  __shared__ float sv[NH];
  int b = blockIdx.x >> 3, tg = blockIdx.x & 7;
  int tid = threadIdx.x;
  for (int hh = tid; hh < NH; hh += 256) {
    float q = 0.f;
    for (int s = 0; s < nsplit; s++) q += g_qpart[(size_t)(s*16 + b) * NH + hh];
    sq[hh] = q;
    sv[hh] = v_att[hh];
  }
  __syncthreads();
  int wid = tid >> 5, lane = tid & 31;
  int tt = tg * 8 + wid;
  const float* krow = g_keys + (size_t)(b*NT + tt) * NH;
  float acc = 0.f;
  for (int h0 = lane; h0 < NH; h0 += 32)
    acc += tanhf(krow[h0] + sq[h0]) * sv[h0];
#pragma unroll
  for (int o = 16; o; o >>= 1) acc += __shfl_xor_sync(0xffffffffu, acc, o);
  if (lane == 0) g_scores[b*NT + tt] = (tt < enc_len[b]) ? acc : -1e9f;
}

__global__ __launch_bounds__(256) void softmax_ctx()
{
  __shared__ float sal[NT];
  int b = blockIdx.x >> 2, hc = blockIdx.x & 3;
  int tid = threadIdx.x;
  if (tid < NT) sal[tid] = g_scores[b*NT + tid];
  __syncthreads();
  float mx = -3e38f;
  for (int t2 = 0; t2 < NT; t2++) mx = fmaxf(mx, sal[t2]);
  __syncthreads();
  if (tid < NT) sal[tid] = expf(sal[tid] - mx);
  __syncthreads();
  float sum = 0.f;
  for (int t2 = 0; t2 < NT; t2++) sum += sal[t2];
  float inv = 1.f / sum;
  int h = hc * 256 + tid;
  const float* mb = g_memory + (size_t)b * NT * NH + h;
  float ctx = 0.f;
  for (int t2 = 0; t2 < NT; t2++) ctx += sal[t2] * mb[t2 * NH];
  g_h_ctx[b*2*NH + NH + h] = ctx * inv;
}

__global__ void attn_out(int t, int nsplit, const int* __restrict__ dec_len)
{
  int idx = blockIdx.x * 256 + threadIdx.x;   // 16384
  int b = idx >> 10, j = idx & 1023;
  float a = 0.f;
  for (int s = 0; s < nsplit; s++) a += g_apart[(size_t)(s*16 + b) * NH + j];
  g_attn_h[b*2*NH + j] = a;   // attn carry (unmasked)
  g_dec_out[(size_t)(b*NT + t) * NH + j] = (t >= dec_len[b]) ? 0.f : a;
}

// =====================================================================
// Host launch
// =====================================================================
extern "C" void kernel_launch(void* const* d_in, const int* in_sizes, int n_in,
                              void* d_out, int out_size)
{
  const int*   enc_in      = (const int*)d_in[0];
  const int*   dec_in      = (const int*)d_in[1];
  const int*   enc_len     = (const int*)d_in[2];
  const int*   dec_len     = (const int*)d_in[3];
  const float* embedding   = (const float*)d_in[4];
  const float* enc_kernel  = (const float*)d_in[5];
  const float* enc_bias    = (const float*)d_in[6];
  const float* dec_kernel  = (const float*)d_in[7];
  const float* dec_bias    = (const float*)d_in[8];
  const float* Wm          = (const float*)d_in[9];
  const float* Wq          = (const float*)d_in[10];
  const float* v_att       = (const float*)d_in[11];
  const float* attn_kernel = (const float*)d_in[12];
  const float* out_kernel  = (const float*)d_in[13];
  float* out = (float*)d_out;
  (void)in_sizes; (void)n_in; (void)out_size;

  float *zx_enc, *zx_dec, *mem, *keys, *dec_o, *zpart, *qpart, *apart, *hbuf, *attn_h, *h_ctx;
  cudaGetSymbolAddress((void**)&zx_enc, g_zx_enc);
  cudaGetSymbolAddress((void**)&zx_dec, g_zx_dec);
  cudaGetSymbolAddress((void**)&mem,    g_memory);
  cudaGetSymbolAddress((void**)&keys,   g_keys);
  cudaGetSymbolAddress((void**)&dec_o,  g_dec_out);
  cudaGetSymbolAddress((void**)&zpart,  g_zpart);
  cudaGetSymbolAddress((void**)&qpart,  g_qpart);
  cudaGetSymbolAddress((void**)&apart,  g_apart);
  cudaGetSymbolAddress((void**)&hbuf,   g_h);
  cudaGetSymbolAddress((void**)&attn_h, g_attn_h);
  cudaGetSymbolAddress((void**)&h_ctx,  g_h_ctx);

  const float* enc_Wrec = enc_kernel + (size_t)NE * NG;  // rows E..E+H-1
  const float* dec_Wrec = dec_kernel + (size_t)NE * NG;  // rows E..E+2H-1

  // init state
  zero_state<<<64, 256>>>();

  // Zx precompute: emb-gather GEMMs [1024 x 4096 x 256] with bias
  sgemm_nn<<<dim3(32, 8), 256>>>(NB*NT, NG, NE, embedding, enc_kernel, enc_bias, zx_enc, enc_in);
  sgemm_nn<<<dim3(32, 8), 256>>>(NB*NT, NG, NE, embedding, dec_kernel, dec_bias, zx_dec, dec_in);

  // ---- encoder ----
  for (int t = 0; t < NT; t++) {
    skinny_gemm<<<dim3(32, 8), 256>>>(hbuf, NH, enc_Wrec, NG, zpart, NG, NH);
    enc_step_gates<<<64, 256>>>(t, 8, enc_len);
  }

  // keys = memory @ Wm  [1024 x 1024 x 1024]
  sgemm_nn<<<dim3(8, 8), 256>>>(NB*NT, NH, NH, mem, Wm, nullptr, keys, nullptr);

  // ---- decoder ----
  dec_init<<<128, 256>>>();
  for (int t = 0; t < NT; t++) {
    // z = zx + [attn|h] @ dec_kernel[E:,:]   (K = 2048)
    skinny_gemm<<<dim3(32, 16), 256>>>(attn_h, 2*NH, dec_Wrec, NG, zpart, NG, 2*NH);
    dec_step_gates<<<64, 256>>>(t, 16);
    // query = h2 @ Wq   (K = 1024)
    skinny_gemm<<<dim3(8, 16), 256>>>(h_ctx, 2*NH, Wq, NH, qpart, NH, NH);
    attn_scores<<<128, 256>>>(16, enc_len, v_att);
    softmax_ctx<<<64, 256>>>();
    // attn2 = [h2|context] @ attn_kernel   (K = 2048)
    skinny_gemm<<<dim3(8, 16), 256>>>(h_ctx, 2*NH, attn_kernel, NH, apart, NH, 2*NH);
    attn_out<<<64, 256>>>(t, 16, dec_len);
  }

  // logits = dec_out @ out_kernel  [1024 x 32000 x 1024]
  sgemm_nn<<<dim3(250, 8), 256>>>(NB*NT, NV, NH, dec_o, out_kernel, nullptr, out, nullptr);
}